// round 13
// baseline (speedup 1.0000x reference)
#include <cuda_runtime.h>
#include <cuda_bf16.h>
#include <cstdint>

#define FNUM 32
#define BNUM 2048
#define KNUM 64
#define HNUM 64
#define NBLK 36          // 8*9/2 field-group blocks (groups of 4 fields)
#define BT   128         // batch tile
#define NBT  (BNUM/BT)   // 16

// ---------------- device scratch (no allocations allowed) ----------------
__device__ __nv_bfloat16 g_Vb[(size_t)FNUM * BNUM * KNUM];  // [f][b][k], 8.4 MB
__device__ float g_partial[NBLK * BNUM];

// ---------------- dynamic shared-memory layout (bytes) ----------------
#define SO_AB   0           // 64 f32
#define SO_AH   256         // 64 f32
#define SO_W    1024        // at_w^T [64h x 64k] bf16, XOR-chunk swizzle (8 KB)
#define SO_P    9216        // p tile [8n x 64k] bf16 (row0 = p, rest 0)   (1 KB)
#define SO_T    10240       // 4 I tiles + 2 J slots, 16 KB each           (96 KB)
#define SMEM_TOTAL (SO_T + 6 * 16384)   // 108544 -> 2 CTAs/SM

static __device__ __forceinline__ uint32_t smem_u32(const void* p) {
    uint32_t a;
    asm("{ .reg .u64 t; cvta.to.shared.u64 t, %1; cvt.u32.u64 %0, t; }" : "=r"(a) : "l"(p));
    return a;
}
static __device__ __forceinline__ uint32_t bmul2(uint32_t a, uint32_t b) {
    uint32_t r;
    asm("mul.bf16x2 %0, %1, %2;" : "=r"(r) : "r"(a), "r"(b));
    return r;
}
static __device__ __forceinline__ void ldsm_x4(uint32_t& r0, uint32_t& r1,
                                               uint32_t& r2, uint32_t& r3, uint32_t addr) {
    asm volatile("ldmatrix.sync.aligned.m8n8.x4.shared.b16 {%0,%1,%2,%3}, [%4];"
                 : "=r"(r0), "=r"(r1), "=r"(r2), "=r"(r3) : "r"(addr));
}
static __device__ __forceinline__ void ldsm_x2(uint32_t& r0, uint32_t& r1, uint32_t addr) {
    asm volatile("ldmatrix.sync.aligned.m8n8.x2.shared.b16 {%0,%1}, [%2];"
                 : "=r"(r0), "=r"(r1) : "r"(addr));
}
static __device__ __forceinline__ void mma16816(float* d, const uint32_t* a, const uint32_t* b) {
    asm volatile(
        "mma.sync.aligned.m16n8k16.row.col.f32.bf16.bf16.f32 "
        "{%0,%1,%2,%3}, {%4,%5,%6,%7}, {%8,%9}, {%0,%1,%2,%3};"
        : "+f"(d[0]), "+f"(d[1]), "+f"(d[2]), "+f"(d[3])
        : "r"(a[0]), "r"(a[1]), "r"(a[2]), "r"(a[3]), "r"(b[0]), "r"(b[1]));
}
static __device__ __forceinline__ void cp16(uint32_t dst, const void* src) {
    asm volatile("cp.async.cg.shared.global [%0], [%1], 16;" :: "r"(dst), "l"(src));
}
static __device__ __forceinline__ void cp_commit() {
    asm volatile("cp.async.commit_group;" ::: "memory");
}
static __device__ __forceinline__ void cp_wait0() {
    asm volatile("cp.async.wait_group 0;" ::: "memory");
}

// Async-stage one 128x64 bf16 field tile into SMEM with per-row XOR chunk
// rotation (chunk' = chunk ^ (row&7)) -> conflict-free ldmatrix.
static __device__ __forceinline__ void load_tile_async(uint32_t dstBase,
                                                       const __nv_bfloat16* src, int tid) {
    const char* s = (const char*)src;
#pragma unroll
    for (int it = 0; it < 4; it++) {
        int u = tid + it * 256;                 // uint4 index, < 1024
        int row = u >> 3, c = u & 7;
        cp16(dstBase + row * 128 + ((c ^ (row & 7)) << 4), s + u * 16);
    }
}

// ---------------- kernel 0: gather + fp32->bf16 (8 threads per row) ----------------
__global__ void __launch_bounds__(256) afm_gather(const int* __restrict__ x,
                                                  const float* __restrict__ emb) {
    int t = blockIdx.x * 256 + threadIdx.x;     // < F*B*8
    int row = t >> 3, q = t & 7;
    const float4* src = (const float4*)(emb + (size_t)__ldg(&x[row]) * KNUM) + 2 * q;
    float4 a = __ldg(src);
    float4 b = __ldg(src + 1);
    __nv_bfloat162 c0 = __floats2bfloat162_rn(a.x, a.y);
    __nv_bfloat162 c1 = __floats2bfloat162_rn(a.z, a.w);
    __nv_bfloat162 c2 = __floats2bfloat162_rn(b.x, b.y);
    __nv_bfloat162 c3 = __floats2bfloat162_rn(b.z, b.w);
    uint4 o;
    o.x = *(uint32_t*)&c0; o.y = *(uint32_t*)&c1;
    o.z = *(uint32_t*)&c2; o.w = *(uint32_t*)&c3;
    ((uint4*)(g_Vb + (size_t)row * KNUM))[q] = o;
}

// ---------------- kernel 1: warp-MMA pair MLP, 2 CTAs/SM ----------------
__global__ void __launch_bounds__(256, 2) afm_tc(const float* __restrict__ at_w,
                                                 const float* __restrict__ at_b,
                                                 const float* __restrict__ at_h,
                                                 const float* __restrict__ pvec)
{
    extern __shared__ __align__(1024) char sm[];
    uint32_t smb = smem_u32(sm);
    int tid = threadIdx.x, warp = tid >> 5, lane = tid & 31;

    // field-block decode: blockIdx.y -> (bi <= bj) over 8 groups of 4 fields
    int t = blockIdx.y, bi = 0;
    while (t >= 8 - bi) { t -= 8 - bi; bi++; }
    int bj = bi + t;
    int b0 = blockIdx.x * BT;
    bool diag = (bi == bj);

    float* ab = (float*)(sm + SO_AB);
    float* ah = (float*)(sm + SO_AH);
    if (tid < 64) { ab[tid] = at_b[tid]; ah[tid] = at_h[tid]; }

    // W^T tile [h rows x k cols] bf16, chunk-XOR swizzle
    for (int i = tid; i < KNUM * HNUM; i += 256) {
        int k = i >> 6, h = i & 63;             // at_w[k][h]
        int phys = (k >> 3) ^ (h & 7);
        *(__nv_bfloat16*)(sm + SO_W + h * 128 + phys * 16 + (k & 7) * 2) =
            __float2bfloat16(at_w[i]);
    }
    // p tile: row 0 = p (row-0 swizzle is identity), rows 1-7 zero
    if (tid < 64)
        *(__nv_bfloat16*)(sm + SO_P + tid * 2) = __float2bfloat16(pvec[tid]);
    else if (tid < 120)
        ((uint4*)(sm + SO_P + 128))[tid - 64] = make_uint4(0, 0, 0, 0);

    // async-stage I tiles (slots 0..3) and, off-diag, J0 (slot 4)
#pragma unroll
    for (int f = 0; f < 4; f++)
        load_tile_async(smb + SO_T + f * 16384,
                        g_Vb + (size_t)((bi * 4 + f) * BNUM + b0) * KNUM, tid);
    if (!diag)
        load_tile_async(smb + SO_T + 4 * 16384,
                        g_Vb + (size_t)((bj * 4 + 0) * BNUM + b0) * KNUM, tid);
    cp_commit();
    cp_wait0();
    __syncthreads();

    // ---- B fragments in registers (reused for all pairs) ----
    // Bf[s][j]: kstep s, n-tile j (j<8: h cols j*8..; j==8: p tile)
    uint32_t Bf[4][9][2];
    {
        int r7 = lane & 7, csel = (lane >> 3) & 1;
#pragma unroll
        for (int s = 0; s < 4; s++) {
            int chunk = (2 * s + csel) ^ r7;
#pragma unroll
            for (int j = 0; j < 8; j++)
                ldsm_x2(Bf[s][j][0], Bf[s][j][1],
                        smb + SO_W + (j * 8 + r7) * 128 + (chunk << 4));
            ldsm_x2(Bf[s][8][0], Bf[s][8][1], smb + SO_P + r7 * 128 + (chunk << 4));
        }
    }

    // A-fragment lane addressing (within a 128x64 tile)
    uint32_t aRowOff = (uint32_t)(warp * 16 + (lane & 15)) * 128;
    uint32_t chOff[4];
#pragma unroll
    for (int s = 0; s < 4; s++)
        chOff[s] = (uint32_t)(((2 * s + (lane >> 4)) ^ (lane & 7)) << 4);

    float accLo = 0.f, accHi = 0.f;
    int c0 = (lane & 3) * 2;

    // two-pass pair body (keeps live D-frags at 20 regs for the 128-reg cap)
    auto do_pair = [&](uint32_t aBaseI, uint32_t aBaseJ) {
        float sLo = 0.f, sHi = 0.f, pdLo, pdHi;
        {   // pass A: n-tiles 0..3 + p tile
            float d[5][4];
#pragma unroll
            for (int j = 0; j < 5; j++)
#pragma unroll
                for (int q = 0; q < 4; q++) d[j][q] = 0.f;
#pragma unroll
            for (int s = 0; s < 4; s++) {
                uint32_t vi[4], vj[4], vv[4];
                ldsm_x4(vi[0], vi[1], vi[2], vi[3], aBaseI + chOff[s]);
                ldsm_x4(vj[0], vj[1], vj[2], vj[3], aBaseJ + chOff[s]);
#pragma unroll
                for (int q = 0; q < 4; q++) vv[q] = bmul2(vi[q], vj[q]);
#pragma unroll
                for (int j = 0; j < 4; j++) mma16816(d[j], vv, Bf[s][j]);
                mma16816(d[4], vv, Bf[s][8]);
            }
#pragma unroll
            for (int j = 0; j < 4; j++) {
                float2 abv = *(const float2*)(ab + j * 8 + c0);
                float2 ahv = *(const float2*)(ah + j * 8 + c0);
                sLo = fmaf(fmaxf(d[j][0] + abv.x, 0.f), ahv.x, sLo);
                sLo = fmaf(fmaxf(d[j][1] + abv.y, 0.f), ahv.y, sLo);
                sHi = fmaf(fmaxf(d[j][2] + abv.x, 0.f), ahv.x, sHi);
                sHi = fmaf(fmaxf(d[j][3] + abv.y, 0.f), ahv.y, sHi);
            }
            pdLo = d[4][0];             // valid in lanes with (lane&3)==0
            pdHi = d[4][2];
        }
        {   // pass B: n-tiles 4..7
            float d[4][4];
#pragma unroll
            for (int j = 0; j < 4; j++)
#pragma unroll
                for (int q = 0; q < 4; q++) d[j][q] = 0.f;
#pragma unroll
            for (int s = 0; s < 4; s++) {
                uint32_t vi[4], vj[4], vv[4];
                ldsm_x4(vi[0], vi[1], vi[2], vi[3], aBaseI + chOff[s]);
                ldsm_x4(vj[0], vj[1], vj[2], vj[3], aBaseJ + chOff[s]);
#pragma unroll
                for (int q = 0; q < 4; q++) vv[q] = bmul2(vi[q], vj[q]);
#pragma unroll
                for (int j = 0; j < 4; j++) mma16816(d[j], vv, Bf[s][4 + j]);
            }
#pragma unroll
            for (int j = 0; j < 4; j++) {
                float2 abv = *(const float2*)(ab + (4 + j) * 8 + c0);
                float2 ahv = *(const float2*)(ah + (4 + j) * 8 + c0);
                sLo = fmaf(fmaxf(d[j][0] + abv.x, 0.f), ahv.x, sLo);
                sLo = fmaf(fmaxf(d[j][1] + abv.y, 0.f), ahv.y, sLo);
                sHi = fmaf(fmaxf(d[j][2] + abv.x, 0.f), ahv.x, sHi);
                sHi = fmaf(fmaxf(d[j][3] + abv.y, 0.f), ahv.y, sHi);
            }
        }
        sLo += __shfl_xor_sync(0xffffffffu, sLo, 1);
        sLo += __shfl_xor_sync(0xffffffffu, sLo, 2);
        sHi += __shfl_xor_sync(0xffffffffu, sHi, 1);
        sHi += __shfl_xor_sync(0xffffffffu, sHi, 2);
        accLo = fmaf(sLo, pdLo, accLo);
        accHi = fmaf(sHi, pdHi, accHi);
    };

    if (!diag) {
        for (int jj = 0; jj < 4; jj++) {
            if (jj < 3) {   // prefetch next J into the other slot
                load_tile_async(smb + SO_T + (4 + ((jj + 1) & 1)) * 16384,
                                g_Vb + (size_t)((bj * 4 + jj + 1) * BNUM + b0) * KNUM, tid);
                cp_commit();
            }
            uint32_t aBaseJ = smb + SO_T + (4 + (jj & 1)) * 16384 + aRowOff;
#pragma unroll
            for (int ii = 0; ii < 4; ii++)
                do_pair(smb + SO_T + ii * 16384 + aRowOff, aBaseJ);
            if (jj < 3) { cp_wait0(); __syncthreads(); }
        }
    } else {
#pragma unroll
        for (int jj = 1; jj < 4; jj++) {
            uint32_t aBaseJ = smb + SO_T + jj * 16384 + aRowOff;
#pragma unroll
            for (int ii = 0; ii < 3; ii++)
                if (ii < jj)
                    do_pair(smb + SO_T + ii * 16384 + aRowOff, aBaseJ);
        }
    }

    if ((lane & 3) == 0) {
        int row = warp * 16 + (lane >> 2);
        g_partial[blockIdx.y * BNUM + b0 + row]     = accLo;
        g_partial[blockIdx.y * BNUM + b0 + row + 8] = accHi;
    }
}

// ---------------- kernel 2: warp-per-b first-order FM + reduce + sigmoid ----------------
__global__ void __launch_bounds__(256) afm_finish(const int* __restrict__ x,
                                                  const float* __restrict__ w0,
                                                  const float* __restrict__ w1,
                                                  float* __restrict__ out) {
    int warp = threadIdx.x >> 5, lane = threadIdx.x & 31;
    int b = blockIdx.x * 8 + warp;              // 256 blocks * 8 warps = 2048
    float s = __ldg(&w1[__ldg(&x[lane * BNUM + b])]);   // f = lane (32 fields)
    s += g_partial[lane * BNUM + b];                    // chunk c = lane
    if (lane < NBLK - 32)
        s += g_partial[(32 + lane) * BNUM + b];         // chunks 32..35
#pragma unroll
    for (int off = 16; off > 0; off >>= 1)
        s += __shfl_xor_sync(0xffffffffu, s, off);
    if (lane == 0)
        out[b] = 1.f / (1.f + expf(-(s + w0[0])));
}

extern "C" void kernel_launch(void* const* d_in, const int* in_sizes, int n_in,
                              void* d_out, int out_size) {
    const int*   x     = (const int*)d_in[0];
    const float* emb_v = (const float*)d_in[1];
    const float* at_w  = (const float*)d_in[2];
    const float* at_b  = (const float*)d_in[3];
    const float* at_h  = (const float*)d_in[4];
    const float* p     = (const float*)d_in[5];
    const float* w0    = (const float*)d_in[6];
    const float* w1    = (const float*)d_in[7];
    float* out = (float*)d_out;

    cudaFuncSetAttribute(afm_tc, cudaFuncAttributeMaxDynamicSharedMemorySize, SMEM_TOTAL);

    afm_gather<<<(FNUM * BNUM * 8) / 256, 256>>>(x, emb_v);
    dim3 g1(NBT, NBLK);
    afm_tc<<<g1, 256, SMEM_TOTAL>>>(at_w, at_b, at_h, p);
    afm_finish<<<BNUM / 8, 256>>>(x, w0, w1, out);
}